// round 17
// baseline (speedup 1.0000x reference)
#include <cuda_runtime.h>
#include <cuda_bf16.h>
#include <math.h>
#include <stdint.h>

#define Bsz   2
#define Tseq  2048
#define Cdim  1024
#define Hn    16
#define HD    64
#define BHn   (Bsz*Hn)          // 32
#define MROWS (Bsz*Tseq)        // 4096
#define QKVN  (3*Cdim)          // 3072

// ---- scratch (static device globals; no allocation) ----
// EXACTLY the layout of the R12-passing (918us) kernel: 128.5MB total.
__device__ float g_qkv[(size_t)MROWS * QKVN];     // [B*T, 3C]
__device__ float g_att[(size_t)MROWS * Cdim];     // [B,T,C] pre-projection
__device__ float g_cos[Tseq * 32];
__device__ float g_sin[Tseq * 32];
// bf16 hi/lo split tensors, [bh][t][hd] (Q pre-scaled by 1/8)
__device__ __nv_bfloat16 g_Qhi[(size_t)BHn * Tseq * HD];
__device__ __nv_bfloat16 g_Qlo[(size_t)BHn * Tseq * HD];
__device__ __nv_bfloat16 g_Khi[(size_t)BHn * Tseq * HD];
__device__ __nv_bfloat16 g_Klo[(size_t)BHn * Tseq * HD];
__device__ __nv_bfloat16 g_Vhi[(size_t)BHn * Tseq * HD];
__device__ __nv_bfloat16 g_Vlo[(size_t)BHn * Tseq * HD];
// V transposed: [bh][hd][t]
__device__ __nv_bfloat16 g_VThi[(size_t)BHn * HD * Tseq];
__device__ __nv_bfloat16 g_VTlo[(size_t)BHn * HD * Tseq];

// ======================================================================
// helpers
// ======================================================================
__device__ __forceinline__ void cvt2(float x, float y, uint32_t& hi, uint32_t& lo)
{
    __nv_bfloat16 hx = __float2bfloat16_rn(x);
    __nv_bfloat16 hy = __float2bfloat16_rn(y);
    float rx = x - __bfloat162float(hx);
    float ry = y - __bfloat162float(hy);
    __nv_bfloat16 lx = __float2bfloat16_rn(rx);
    __nv_bfloat16 ly = __float2bfloat16_rn(ry);
    hi = (uint32_t)__bfloat16_as_ushort(hx) | ((uint32_t)__bfloat16_as_ushort(hy) << 16);
    lo = (uint32_t)__bfloat16_as_ushort(lx) | ((uint32_t)__bfloat16_as_ushort(ly) << 16);
}

__device__ __forceinline__ void split2(float x, __nv_bfloat16& h, __nv_bfloat16& l)
{
    h = __float2bfloat16_rn(x);
    l = __float2bfloat16_rn(x - __bfloat162float(h));
}

__device__ __forceinline__ void mma_bf16(float* d, const uint32_t* a, const uint32_t* b)
{
    asm volatile(
        "mma.sync.aligned.m16n8k16.row.col.f32.bf16.bf16.f32 "
        "{%0,%1,%2,%3}, {%4,%5,%6,%7}, {%8,%9}, {%0,%1,%2,%3};"
        : "+f"(d[0]), "+f"(d[1]), "+f"(d[2]), "+f"(d[3])
        : "r"(a[0]), "r"(a[1]), "r"(a[2]), "r"(a[3]), "r"(b[0]), "r"(b[1]));
}

// ======================================================================
// Tensor-core GEMM via mma.sync bf16, 3-product hi/lo split (exact to
// ~1e-5): C[M,N] = A[M,K] * B[N,K]^T, fp32 in/out.
// CTA: 128x64 C tile, 256 threads (8 warps of 32x32), K chunks of 32.
// smem rows padded to 36 words -> conflict-free fragment LDS.
// Inner loop loads each hi/lo fragment set ONCE per ks (was 3x).
// MODE 0: A = x (param), C = g_qkv.   MODE 1: A = g_att, C = out.
// ======================================================================
#define PADW 36    // words per smem row (72 bf16: 32 hi | 32 lo | 8 pad)

template<int MODE>
__global__ void __launch_bounds__(256, 2) gemm_bf(const float* __restrict__ Aext,
                                                  const float* __restrict__ Bm,
                                                  float* __restrict__ Cext,
                                                  int M, int N, int K)
{
    const float* A  = (MODE == 0) ? Aext : (const float*)g_att;
    float*       Cm = (MODE == 0) ? (float*)g_qkv : Cext;

    __shared__ uint32_t As[128 * PADW];   // 18432 B
    __shared__ uint32_t Bs[64 * PADW];    //  9216 B

    const int tid  = threadIdx.x;
    const int wid  = tid >> 5;
    const int lane = tid & 31;
    const int g    = lane >> 2;      // fragment group row
    const int i4   = lane & 3;       // fragment k pair
    const int wm   = wid & 3;        // warp row (32 rows each)
    const int wn   = wid >> 2;       // warp col (32 cols each)

    const int rowBase = blockIdx.y * 128;
    const int colBase = blockIdx.x * 64;

    // loader geometry
    const int ar = tid >> 1, ah = tid & 1;          // A: row, 16-col half
    const int br = tid >> 2, bq = tid & 3;          // B: row, 8-col quarter
    const float* Aptr = A  + (size_t)(rowBase + ar) * K + ah * 16;
    const float* Bptr = Bm + (size_t)(colBase + br) * K + bq * 8;

    float acc[2][4][4];
    #pragma unroll
    for (int mi = 0; mi < 2; ++mi)
        #pragma unroll
        for (int ni = 0; ni < 4; ++ni)
            #pragma unroll
            for (int q = 0; q < 4; ++q) acc[mi][ni][q] = 0.f;

    // prefetch chunk 0
    float4 pa[4], pb[2];
    #pragma unroll
    for (int q = 0; q < 4; ++q)
        pa[q] = *reinterpret_cast<const float4*>(Aptr + q * 4);
    #pragma unroll
    for (int q = 0; q < 2; ++q)
        pb[q] = *reinterpret_cast<const float4*>(Bptr + q * 4);

    const int NCHUNK = K / 32;
    for (int c = 0; c < NCHUNK; ++c) {
        // ---- convert prefetched regs into smem hi|lo ----
        {
            uint32_t* aw = As + ar * PADW + ah * 8;
            #pragma unroll
            for (int q = 0; q < 4; ++q) {
                uint32_t h0, l0, h1, l1;
                cvt2(pa[q].x, pa[q].y, h0, l0);
                cvt2(pa[q].z, pa[q].w, h1, l1);
                aw[q * 2]          = h0;
                aw[q * 2 + 1]      = h1;
                aw[q * 2 + 16]     = l0;
                aw[q * 2 + 17]     = l1;
            }
            uint32_t* bw = Bs + br * PADW + bq * 4;
            #pragma unroll
            for (int q = 0; q < 2; ++q) {
                uint32_t h0, l0, h1, l1;
                cvt2(pb[q].x, pb[q].y, h0, l0);
                cvt2(pb[q].z, pb[q].w, h1, l1);
                bw[q * 2]          = h0;
                bw[q * 2 + 1]      = h1;
                bw[q * 2 + 16]     = l0;
                bw[q * 2 + 17]     = l1;
            }
        }
        __syncthreads();

        if (c + 1 < NCHUNK) {   // prefetch next chunk (flies during MMA)
            #pragma unroll
            for (int q = 0; q < 4; ++q)
                pa[q] = *reinterpret_cast<const float4*>(Aptr + (c + 1) * 32 + q * 4);
            #pragma unroll
            for (int q = 0; q < 2; ++q)
                pb[q] = *reinterpret_cast<const float4*>(Bptr + (c + 1) * 32 + q * 4);
        }

        // ---- per ks: load hi+lo fragments once, then 3 products ----
        #pragma unroll
        for (int ks = 0; ks < 2; ++ks) {
            const int kw = ks * 8 + i4;
            uint32_t a_h[2][4], a_l[2][4], b_h[4][2], b_l[4][2];
            #pragma unroll
            for (int mi = 0; mi < 2; ++mi) {
                const uint32_t* base = As + (wm * 32 + mi * 16 + g) * PADW + kw;
                a_h[mi][0] = base[0];
                a_h[mi][1] = base[8 * PADW];
                a_h[mi][2] = base[4];
                a_h[mi][3] = base[8 * PADW + 4];
                a_l[mi][0] = base[16];
                a_l[mi][1] = base[8 * PADW + 16];
                a_l[mi][2] = base[20];
                a_l[mi][3] = base[8 * PADW + 20];
            }
            #pragma unroll
            for (int ni = 0; ni < 4; ++ni) {
                const uint32_t* base = Bs + (wn * 32 + ni * 8 + g) * PADW + kw;
                b_h[ni][0] = base[0];
                b_h[ni][1] = base[4];
                b_l[ni][0] = base[16];
                b_l[ni][1] = base[20];
            }
            #pragma unroll
            for (int mi = 0; mi < 2; ++mi)
                #pragma unroll
                for (int ni = 0; ni < 4; ++ni) {
                    mma_bf16(acc[mi][ni], a_h[mi], b_h[ni]);   // Ahi*Bhi
                    mma_bf16(acc[mi][ni], a_h[mi], b_l[ni]);   // Ahi*Blo
                    mma_bf16(acc[mi][ni], a_l[mi], b_h[ni]);   // Alo*Bhi
                }
        }
        __syncthreads();
    }

    // ---- epilogue: fragment layout -> global ----
    #pragma unroll
    for (int mi = 0; mi < 2; ++mi) {
        #pragma unroll
        for (int ni = 0; ni < 4; ++ni) {
            int row = rowBase + wm * 32 + mi * 16 + g;
            int col = colBase + wn * 32 + ni * 8 + 2 * i4;
            float* c0 = Cm + (size_t)row * N + col;
            c0[0] = acc[mi][ni][0];
            c0[1] = acc[mi][ni][1];
            float* c2 = c0 + 8 * N;
            c2[0] = acc[mi][ni][2];
            c2[1] = acc[mi][ni][3];
        }
    }
}

// ======================================================================
// RoPE tables (double precision, tiny)
// ======================================================================
__global__ void rope_table_kernel()
{
    int idx = blockIdx.x * blockDim.x + threadIdx.x;
    int j = idx & 31;
    int t = idx >> 5;
    double invf = exp(-(double)j * (9.210340371976184 / 32.0));
    double sd, cd;
    sincos((double)t * invf, &sd, &cd);
    g_cos[idx] = (float)cd;
    g_sin[idx] = (float)sd;
}

// ======================================================================
// RoPE + QKV split/transpose -> bf16 hi/lo arrays (Q pre-scaled 1/8)
// ======================================================================
__global__ void rope_kernel()
{
    int idx = blockIdx.x * blockDim.x + threadIdx.x;
    int j = idx & 31;
    int h = (idx >> 5) & (Hn - 1);
    int t = (idx >> 9) & (Tseq - 1);
    int b = idx >> 20;

    size_t base = (size_t)(b * Tseq + t) * QKVN;
    int qo = h * HD + j;

    float c = g_cos[(t << 5) + j];
    float s = g_sin[(t << 5) + j];

    size_t o = ((size_t)(b * Hn + h) * Tseq + t) * HD + j;

    float q0 = g_qkv[base + qo];
    float q1 = g_qkv[base + qo + 32];
    float qr0 = (q0 * c - q1 * s) * 0.125f;
    float qr1 = (q1 * c + q0 * s) * 0.125f;
    split2(qr0, g_Qhi[o],      g_Qlo[o]);
    split2(qr1, g_Qhi[o + 32], g_Qlo[o + 32]);

    float k0 = g_qkv[base + Cdim + qo];
    float k1 = g_qkv[base + Cdim + qo + 32];
    split2(k0 * c - k1 * s, g_Khi[o],      g_Klo[o]);
    split2(k1 * c + k0 * s, g_Khi[o + 32], g_Klo[o + 32]);

    split2(g_qkv[base + 2 * Cdim + qo],      g_Vhi[o],      g_Vlo[o]);
    split2(g_qkv[base + 2 * Cdim + qo + 32], g_Vhi[o + 32], g_Vlo[o + 32]);
}

// ======================================================================
// V transpose: [bh][t][hd] -> [bh][hd][t], tiled through smem.
// grid (Tseq/64, BHn), 128 threads.
// ======================================================================
__global__ void vtrans_kernel()
{
    __shared__ unsigned short sh[64 * 66], sl[64 * 66];
    const int tb = blockIdx.x * 64;
    const int bh = blockIdx.y;
    const int tid = threadIdx.x;
    const int wid = tid >> 5, lane = tid & 31;
    const int r = tid >> 1, hf = tid & 1;

    const uint32_t* srch = (const uint32_t*)(g_Vhi + ((size_t)bh * Tseq + tb + r) * HD) + hf * 16;
    const uint32_t* srcl = (const uint32_t*)(g_Vlo + ((size_t)bh * Tseq + tb + r) * HD) + hf * 16;
    uint32_t* dh = (uint32_t*)(sh + r * 66 + hf * 32);
    uint32_t* dl = (uint32_t*)(sl + r * 66 + hf * 32);
    #pragma unroll
    for (int u = 0; u < 16; ++u) { dh[u] = srch[u]; dl[u] = srcl[u]; }
    __syncthreads();

    #pragma unroll
    for (int it = 0; it < 16; ++it) {
        int d = it * 4 + wid;
        uint32_t vh = (uint32_t)sh[(2 * lane) * 66 + d] |
                      ((uint32_t)sh[(2 * lane + 1) * 66 + d] << 16);
        uint32_t vl = (uint32_t)sl[(2 * lane) * 66 + d] |
                      ((uint32_t)sl[(2 * lane + 1) * 66 + d] << 16);
        ((uint32_t*)(g_VThi + ((size_t)bh * HD + d) * Tseq + tb))[lane] = vh;
        ((uint32_t*)(g_VTlo + ((size_t)bh * HD + d) * Tseq + tb))[lane] = vl;
    }
}

// ======================================================================
// Flash attention via mma.sync bf16 (3-product hi/lo split), causal.
// 128 threads = 4 warps; warp owns 16 q rows; Br=Bc=64.
// K tiles natural [key][hd]; V tiles from VT [hd][key]. P stays in regs.
// ======================================================================
#define ATP 36   // words per smem row (64 bf16 = 32 words + 4 pad)

__global__ void __launch_bounds__(128) attn_kernel()
{
    __shared__ uint32_t Kh[64 * ATP], Kl[64 * ATP];
    __shared__ uint32_t Vh[64 * ATP], Vl[64 * ATP];

    const int qtile = gridDim.x - 1 - blockIdx.x;   // longest first
    const int bh    = blockIdx.y;
    const int tid   = threadIdx.x;
    const int wid   = tid >> 5;
    const int lane  = tid & 31;
    const int g     = lane >> 2;
    const int i4    = lane & 3;

    // ---- Q fragments from global (hi/lo), rows wid*16 + {g, g+8} ----
    uint32_t qh[4][4], ql[4][4];
    {
        const __nv_bfloat16* Qhp = g_Qhi + ((size_t)bh * Tseq + qtile * 64 + wid * 16) * HD;
        const __nv_bfloat16* Qlp = g_Qlo + ((size_t)bh * Tseq + qtile * 64 + wid * 16) * HD;
        #pragma unroll
        for (int kc = 0; kc < 4; ++kc) {
            int e0 = kc * 16 + 2 * i4;
            qh[kc][0] = *(const uint32_t*)(Qhp + g * HD + e0);
            qh[kc][1] = *(const uint32_t*)(Qhp + (g + 8) * HD + e0);
            qh[kc][2] = *(const uint32_t*)(Qhp + g * HD + e0 + 8);
            qh[kc][3] = *(const uint32_t*)(Qhp + (g + 8) * HD + e0 + 8);
            ql[kc][0] = *(const uint32_t*)(Qlp + g * HD + e0);
            ql[kc][1] = *(const uint32_t*)(Qlp + (g + 8) * HD + e0);
            ql[kc][2] = *(const uint32_t*)(Qlp + g * HD + e0 + 8);
            ql[kc][3] = *(const uint32_t*)(Qlp + (g + 8) * HD + e0 + 8);
        }
    }

    float acc[8][4];
    #pragma unroll
    for (int nf = 0; nf < 8; ++nf)
        #pragma unroll
        for (int q = 0; q < 4; ++q) acc[nf][q] = 0.f;
    float m0 = -1e30f, m1 = -1e30f, l0 = 0.f, l1 = 0.f;

    const int r = tid >> 1, hf = tid & 1;   // tile loader geometry

    for (int t0 = 0; t0 <= qtile; ++t0) {
        const int kbase = t0 * 64;
        __syncthreads();
        {   // load K hi/lo [key][hd] and VT hi/lo [hd][key] tiles
            const uint4* ksh = (const uint4*)(g_Khi + ((size_t)bh * Tseq + kbase + r) * HD + hf * 32);
            const uint4* ksl = (const uint4*)(g_Klo + ((size_t)bh * Tseq + kbase + r) * HD + hf * 32);
            const uint4* vsh = (const uint4*)(g_VThi + ((size_t)bh * HD + r) * Tseq + kbase + hf * 32);
            const uint4* vsl = (const uint4*)(g_VTlo + ((size_t)bh * HD + r) * Tseq + kbase + hf * 32);
            uint4* kdh = (uint4*)(Kh + r * ATP + hf * 16);
            uint4* kdl = (uint4*)(Kl + r * ATP + hf * 16);
            uint4* vdh = (uint4*)(Vh + r * ATP + hf * 16);
            uint4* vdl = (uint4*)(Vl + r * ATP + hf * 16);
            #pragma unroll
            for (int q = 0; q < 4; ++q) {
                kdh[q] = ksh[q];
                kdl[q] = ksl[q];
                vdh[q] = vsh[q];
                vdl[q] = vsl[q];
            }
        }
        __syncthreads();

        // ---- QK: S(16x64) fragments ----
        float S[8][4];
        #pragma unroll
        for (int nf = 0; nf < 8; ++nf)
            #pragma unroll
            for (int q = 0; q < 4; ++q) S[nf][q] = 0.f;

        #pragma unroll
        for (int kc = 0; kc < 4; ++kc) {
            #pragma unroll
            for (int nf = 0; nf < 8; ++nf) {
                const uint32_t* kb  = Kh + (nf * 8 + g) * ATP + kc * 8 + i4;
                const uint32_t* kbl = Kl + (nf * 8 + g) * ATP + kc * 8 + i4;
                uint32_t bhF[2] = {kb[0], kb[4]};
                uint32_t blF[2] = {kbl[0], kbl[4]};
                mma_bf16(S[nf], qh[kc], bhF);
                mma_bf16(S[nf], qh[kc], blF);
                mma_bf16(S[nf], ql[kc], bhF);
            }
        }

        // ---- causal mask on diagonal tile ----
        if (t0 == qtile) {
            const int r0 = wid * 16 + g, r1 = r0 + 8;
            #pragma unroll
            for (int nf = 0; nf < 8; ++nf) {
                int c0 = nf * 8 + 2 * i4, c1 = c0 + 1;
                if (c0 > r0) S[nf][0] = -1e30f;
                if (c1 > r0) S[nf][1] = -1e30f;
                if (c0 > r1) S[nf][2] = -1e30f;
                if (c1 > r1) S[nf][3] = -1e30f;
            }
        }

        // ---- online softmax (stats replicated over the 4 i4 lanes) ----
        float t0max = -1e30f, t1max = -1e30f;
        #pragma unroll
        for (int nf = 0; nf < 8; ++nf) {
            t0max = fmaxf(t0max, fmaxf(S[nf][0], S[nf][1]));
            t1max = fmaxf(t1max, fmaxf(S[nf][2], S[nf][3]));
        }
        t0max = fmaxf(t0max, __shfl_xor_sync(0xffffffffu, t0max, 1));
        t0max = fmaxf(t0max, __shfl_xor_sync(0xffffffffu, t0max, 2));
        t1max = fmaxf(t1max, __shfl_xor_sync(0xffffffffu, t1max, 1));
        t1max = fmaxf(t1max, __shfl_xor_sync(0xffffffffu, t1max, 2));

        float mn0 = fmaxf(m0, t0max), mn1 = fmaxf(m1, t1max);
        float cr0 = __expf(m0 - mn0), cr1 = __expf(m1 - mn1);
        m0 = mn0; m1 = mn1;
        l0 *= cr0; l1 *= cr1;
        #pragma unroll
        for (int nf = 0; nf < 8; ++nf) {
            acc[nf][0] *= cr0; acc[nf][1] *= cr0;
            acc[nf][2] *= cr1; acc[nf][3] *= cr1;
        }

        float ps0 = 0.f, ps1 = 0.f;
        #pragma unroll
        for (int nf = 0; nf < 8; ++nf) {
            S[nf][0] = __expf(S[nf][0] - mn0); ps0 += S[nf][0];
            S[nf][1] = __expf(S[nf][1] - mn0); ps0 += S[nf][1];
            S[nf][2] = __expf(S[nf][2] - mn1); ps1 += S[nf][2];
            S[nf][3] = __expf(S[nf][3] - mn1); ps1 += S[nf][3];
        }
        ps0 += __shfl_xor_sync(0xffffffffu, ps0, 1);
        ps0 += __shfl_xor_sync(0xffffffffu, ps0, 2);
        ps1 += __shfl_xor_sync(0xffffffffu, ps1, 1);
        ps1 += __shfl_xor_sync(0xffffffffu, ps1, 2);
        l0 += ps0; l1 += ps1;

        // ---- PV: P (registers) x V^T tiles ----
        #pragma unroll
        for (int kc = 0; kc < 4; ++kc) {
            uint32_t pah[4], pal[4];
            cvt2(S[2 * kc][0],     S[2 * kc][1],     pah[0], pal[0]);
            cvt2(S[2 * kc][2],     S[2 * kc][3],     pah[1], pal[1]);
            cvt2(S[2 * kc + 1][0], S[2 * kc + 1][1], pah[2], pal[2]);
            cvt2(S[2 * kc + 1][2], S[2 * kc + 1][3], pah[3], pal[3]);
            #pragma unroll
            for (int onf = 0; onf < 8; ++onf) {
                const uint32_t* vb  = Vh + (onf * 8 + g) * ATP + kc * 8 + i4;
                const uint32_t* vbl = Vl + (onf * 8 + g) * ATP + kc * 8 + i4;
                uint32_t bhF[2] = {vb[0], vb[4]};
                uint32_t blF[2] = {vbl[0], vbl[4]};
                mma_bf16(acc[onf], pah, bhF);
                mma_bf16(acc[onf], pah, blF);
                mma_bf16(acc[onf], pal, bhF);
            }
        }
    }

    // ---- output ----
    const float inv0 = 1.f / l0, inv1 = 1.f / l1;
    const int b = bh >> 4;
    const int h = bh & 15;
    const int row0 = qtile * 64 + wid * 16 + g;
    #pragma unroll
    for (int onf = 0; onf < 8; ++onf) {
        int col = h * HD + onf * 8 + 2 * i4;
        float* o0 = g_att + (size_t)(b * Tseq + row0) * Cdim + col;
        o0[0] = acc[onf][0] * inv0;
        o0[1] = acc[onf][1] * inv0;
        float* o1 = g_att + (size_t)(b * Tseq + row0 + 8) * Cdim + col;
        o1[0] = acc[onf][2] * inv1;
        o1[1] = acc[onf][3] * inv1;
    }
}

// ======================================================================
extern "C" void kernel_launch(void* const* d_in, const int* in_sizes, int n_in,
                              void* d_out, int out_size)
{
    const float* x      = (const float*)d_in[0];
    const float* w_attn = (const float*)d_in[1];
    const float* w_proj = (const float*)d_in[2];
    float* out = (float*)d_out;

    rope_table_kernel<<<(Tseq * 32) / 256, 256>>>();

    gemm_bf<0><<<dim3(QKVN / 64, MROWS / 128), 256>>>(x, w_attn, nullptr,
                                                      MROWS, QKVN, Cdim);

    rope_kernel<<<(Bsz * Tseq * Hn * 32) / 256, 256>>>();

    vtrans_kernel<<<dim3(Tseq / 64, BHn), 128>>>();

    attn_kernel<<<dim3(Tseq / 64, BHn), 128>>>();

    gemm_bf<1><<<dim3(Cdim / 64, MROWS / 128), 256>>>(nullptr, w_proj, out,
                                                      MROWS, Cdim, Cdim);
}